// round 4
// baseline (speedup 1.0000x reference)
#include <cuda_runtime.h>

// EdgewiseReduce: out[n, :] = sum_{e : edge_center[e] == n} edge_feat[e, :]
// edge_center (= edge_index[0]) is SORTED ascending.
//
// Pass 1 (build_offsets): vectorized (4 keys/thread) CSR row_offsets from the
//                         sorted key array. g_offsets[n] = first edge with
//                         center >= n; g_offsets[N] = E.
// Pass 2 (reduce): ONE WARP PER NODE. 32 lanes x float2 = full 64-float row,
//                  perfectly coalesced 256B per edge. Register accumulation,
//                  single plain store. No atomics, no memset, and no intra-warp
//                  pairing of nodes (removes max(deg1,deg2) imbalance).
//
// Inputs (metadata order):
//   d_in[0] = edge_index  [2, E]  int64 (or int32; runtime-detected)
//   d_in[1] = edge_feat   [E, 64] float32
//   d_in[2] = node_types  [N, 1]
// Output: [N, 64] float32

#define D_FEAT 64
#define BLOCK_THREADS 256
#define WARPS_PER_BLOCK (BLOCK_THREADS / 32)
#define KEYS_PER_THREAD 4
#define MAX_NODES_P1 (1 << 21)

__device__ int g_offsets[MAX_NODES_P1];

// ---------------- Pass 1: CSR offsets from sorted keys (vectorized) --------
__global__ void __launch_bounds__(256)
build_offsets_kernel(const void* __restrict__ edge_index, int E, int N)
{
    // dtype detection: an int64 read of an int32 buffer fuses two indices ->
    // value >= 2^32 >> N with overwhelming probability across 3 probes.
    __shared__ int s_is64;
    if (threadIdx.x == 0) {
        const long long* p64 = (const long long*)edge_index;
        unsigned long long v0 = (unsigned long long)p64[E / 3];
        unsigned long long v1 = (unsigned long long)p64[E / 2];
        unsigned long long v2 = (unsigned long long)p64[E - 1];
        unsigned long long nn = (unsigned long long)N;
        s_is64 = (v0 < nn && v1 < nn && v2 < nn) ? 1 : 0;
    }
    __syncthreads();
    const bool is64 = (s_is64 != 0);

    const long long* __restrict__ p64 = (const long long*)edge_index;
    const int*       __restrict__ p32 = (const int*)edge_index;

    const int base = (blockIdx.x * blockDim.x + threadIdx.x) * KEYS_PER_THREAD;
    if (base >= E) return;

    int k[KEYS_PER_THREAD];
    int nvalid;
    if (base + KEYS_PER_THREAD <= E) {
        nvalid = KEYS_PER_THREAD;
        if (is64) {
            // 2 x 16B vector loads (no __ldg overload for longlong4; plain
            // deref through __restrict__ compiles to LDG.E.128 anyway)
            longlong2 v0 = ((const longlong2*)p64)[(base >> 1) + 0];
            longlong2 v1 = ((const longlong2*)p64)[(base >> 1) + 1];
            k[0] = (int)v0.x; k[1] = (int)v0.y; k[2] = (int)v1.x; k[3] = (int)v1.y;
        } else {
            int4 v = ((const int4*)p32)[base >> 2];
            k[0] = v.x; k[1] = v.y; k[2] = v.z; k[3] = v.w;
        }
    } else {
        nvalid = E - base;
        for (int j = 0; j < nvalid; ++j)
            k[j] = is64 ? (int)p64[base + j] : p32[base + j];
    }

    int prev;
    if (base == 0) prev = -1;
    else prev = is64 ? (int)p64[base - 1] : p32[base - 1];

    #pragma unroll
    for (int j = 0; j < KEYS_PER_THREAD; ++j) {
        if (j < nvalid) {
            const int c = k[j];
            for (int n = prev + 1; n <= c; ++n) g_offsets[n] = base + j;
            prev = c;
        }
    }

    // Tail: nodes beyond the last key get empty ranges ending at E.
    if (base + nvalid == E) {
        for (int n = prev + 1; n <= N; ++n) g_offsets[n] = E;
    }
}

// ---------------- Pass 2: one warp per node, float2 lanes ------------------
__global__ void __launch_bounds__(BLOCK_THREADS)
edgewise_reduce_kernel(const float2* __restrict__ feat,   // [E * 32]
                       float2* __restrict__ out,          // [N * 32]
                       int N)
{
    const int lane = threadIdx.x & 31;
    const int warp = threadIdx.x >> 5;
    const int node = blockIdx.x * WARPS_PER_BLOCK + warp;
    if (node >= N) return;

    const int start = g_offsets[node];
    const int end   = g_offsets[node + 1];

    float2 acc = make_float2(0.f, 0.f);
    int e = start;
    #pragma unroll 1
    for (; e + 4 <= end; e += 4) {
        float2 a = __ldg(&feat[(long long)(e + 0) * 32 + lane]);
        float2 b = __ldg(&feat[(long long)(e + 1) * 32 + lane]);
        float2 c = __ldg(&feat[(long long)(e + 2) * 32 + lane]);
        float2 d = __ldg(&feat[(long long)(e + 3) * 32 + lane]);
        acc.x += (a.x + b.x) + (c.x + d.x);
        acc.y += (a.y + b.y) + (c.y + d.y);
    }
    for (; e < end; ++e) {
        float2 a = __ldg(&feat[(long long)e * 32 + lane]);
        acc.x += a.x; acc.y += a.y;
    }

    out[(long long)node * 32 + lane] = acc;
}

extern "C" void kernel_launch(void* const* d_in, const int* in_sizes, int n_in,
                              void* d_out, int out_size)
{
    const void*   edge_index = d_in[0];
    const float2* feat       = (const float2*)d_in[1];
    float2*       out        = (float2*)d_out;

    const int E = in_sizes[1] / D_FEAT;
    const int N = out_size / D_FEAT;

    const int p1_threads = (E + KEYS_PER_THREAD - 1) / KEYS_PER_THREAD;
    build_offsets_kernel<<<(p1_threads + 255) / 256, 256>>>(edge_index, E, N);

    const int grid = (N + WARPS_PER_BLOCK - 1) / WARPS_PER_BLOCK;
    edgewise_reduce_kernel<<<grid, BLOCK_THREADS>>>(feat, out, N);
}

// round 5
// speedup vs baseline: 1.0639x; 1.0639x over previous
#include <cuda_runtime.h>

// EdgewiseReduce: out[n, :] = sum_{e : edge_center[e] == n} edge_feat[e, :]
// edge_center (= edge_index[0]) is SORTED ascending.
//
// Pass 1 (build_offsets): vectorized (4 keys/thread) CSR row_offsets.
//   g_offsets[n] = first edge with center >= n; g_offsets[N] = E.
// Pass 2 (reduce): one 16-lane group per node; float4 lanes (full 64-float row
//   = 256B coalesced per edge). Predicated 8-deep unrolled accumulation: every
//   iteration issues 8 independent LDG.128 per thread (128B in flight), with
//   per-load predication covering the remainder (no serial scalar tail).
//   No atomics, no memset.
//
// Inputs (metadata order):
//   d_in[0] = edge_index  [2, E]  int64 (or int32; runtime-detected)
//   d_in[1] = edge_feat   [E, 64] float32
//   d_in[2] = node_types  [N, 1]
// Output: [N, 64] float32

#define D_FEAT 64
#define LANES 16                               // 16 lanes x float4 = 64 floats
#define BLOCK_THREADS 256
#define GROUPS_PER_BLOCK (BLOCK_THREADS / LANES)
#define KEYS_PER_THREAD 4
#define UNROLL 8
#define MAX_NODES_P1 (1 << 21)

__device__ int g_offsets[MAX_NODES_P1];

// ---------------- Pass 1: CSR offsets from sorted keys (vectorized) --------
__global__ void __launch_bounds__(256)
build_offsets_kernel(const void* __restrict__ edge_index, int E, int N)
{
    // dtype detection: an int64 read of an int32 buffer fuses two indices ->
    // value >= 2^32 >> N with overwhelming probability across 3 probes.
    __shared__ int s_is64;
    if (threadIdx.x == 0) {
        const long long* q = (const long long*)edge_index;
        unsigned long long v0 = (unsigned long long)q[E / 3];
        unsigned long long v1 = (unsigned long long)q[E / 2];
        unsigned long long v2 = (unsigned long long)q[E - 1];
        unsigned long long nn = (unsigned long long)N;
        s_is64 = (v0 < nn && v1 < nn && v2 < nn) ? 1 : 0;
    }
    __syncthreads();
    const bool is64 = (s_is64 != 0);

    const long long* __restrict__ p64 = (const long long*)edge_index;
    const int*       __restrict__ p32 = (const int*)edge_index;

    const int base = (blockIdx.x * blockDim.x + threadIdx.x) * KEYS_PER_THREAD;
    if (base >= E) return;

    int k[KEYS_PER_THREAD];
    int nvalid;
    if (base + KEYS_PER_THREAD <= E) {
        nvalid = KEYS_PER_THREAD;
        if (is64) {
            longlong2 v0 = ((const longlong2*)p64)[(base >> 1) + 0];
            longlong2 v1 = ((const longlong2*)p64)[(base >> 1) + 1];
            k[0] = (int)v0.x; k[1] = (int)v0.y; k[2] = (int)v1.x; k[3] = (int)v1.y;
        } else {
            int4 v = ((const int4*)p32)[base >> 2];
            k[0] = v.x; k[1] = v.y; k[2] = v.z; k[3] = v.w;
        }
    } else {
        nvalid = E - base;
        for (int j = 0; j < nvalid; ++j)
            k[j] = is64 ? (int)p64[base + j] : p32[base + j];
    }

    int prev;
    if (base == 0) prev = -1;
    else prev = is64 ? (int)p64[base - 1] : p32[base - 1];

    #pragma unroll
    for (int j = 0; j < KEYS_PER_THREAD; ++j) {
        if (j < nvalid) {
            const int c = k[j];
            for (int n = prev + 1; n <= c; ++n) g_offsets[n] = base + j;
            prev = c;
        }
    }

    if (base + nvalid == E) {
        for (int n = prev + 1; n <= N; ++n) g_offsets[n] = E;
    }
}

// ---------------- Pass 2: node-centric segmented sum, MLP=8 ----------------
__global__ void __launch_bounds__(BLOCK_THREADS)
edgewise_reduce_kernel(const float4* __restrict__ feat,   // [E * LANES]
                       float4* __restrict__ out,          // [N * LANES]
                       int N)
{
    const int lane  = threadIdx.x & (LANES - 1);
    const int group = threadIdx.x / LANES;
    const int node  = blockIdx.x * GROUPS_PER_BLOCK + group;
    if (node >= N) return;

    const int start = g_offsets[node];
    const int end   = g_offsets[node + 1];

    float4 acc0 = make_float4(0.f, 0.f, 0.f, 0.f);
    float4 acc1 = make_float4(0.f, 0.f, 0.f, 0.f);

    #pragma unroll 1
    for (int e = start; e < end; e += UNROLL) {
        // 8 independent predicated loads -> 128B in flight per thread.
        #pragma unroll
        for (int i = 0; i < UNROLL; ++i) {
            if (e + i < end) {
                float4 v = __ldg(&feat[(long long)(e + i) * LANES + lane]);
                if (i & 1) {
                    acc1.x += v.x; acc1.y += v.y; acc1.z += v.z; acc1.w += v.w;
                } else {
                    acc0.x += v.x; acc0.y += v.y; acc0.z += v.z; acc0.w += v.w;
                }
            }
        }
    }

    float4 r;
    r.x = acc0.x + acc1.x;
    r.y = acc0.y + acc1.y;
    r.z = acc0.z + acc1.z;
    r.w = acc0.w + acc1.w;
    out[(long long)node * LANES + lane] = r;
}

extern "C" void kernel_launch(void* const* d_in, const int* in_sizes, int n_in,
                              void* d_out, int out_size)
{
    const void*   edge_index = d_in[0];
    const float4* feat       = (const float4*)d_in[1];
    float4*       out        = (float4*)d_out;

    const int E = in_sizes[1] / D_FEAT;
    const int N = out_size / D_FEAT;

    const int p1_threads = (E + KEYS_PER_THREAD - 1) / KEYS_PER_THREAD;
    build_offsets_kernel<<<(p1_threads + 255) / 256, 256>>>(edge_index, E, N);

    const int grid = (N + GROUPS_PER_BLOCK - 1) / GROUPS_PER_BLOCK;
    edgewise_reduce_kernel<<<grid, BLOCK_THREADS>>>(feat, out, N);
}

// round 6
// speedup vs baseline: 1.1058x; 1.0394x over previous
#include <cuda_runtime.h>

// EdgewiseReduce: out[n, :] = sum_{e : edge_center[e] == n} edge_feat[e, :]
// edge_center (= edge_index[0]) is SORTED ascending.
//
// Pass 1 (build_offsets): vectorized (4 keys/thread) CSR row_offsets.
//   prev-key obtained via __shfl_up from the neighbor thread (only lane 0 of
//   each warp does an extra scalar load). g_offsets[n] = first edge with
//   center >= n; g_offsets[N] = E.
// Pass 2 (reduce): ONE WARP PER NODE, float4 lanes over TWO edges per step:
//   lanes 0-15 hold edge e's 64-float row, lanes 16-31 hold edge e+1's.
//   512B per warp per step, 8 steps unrolled (16 edges, 128B/thread in
//   flight), per-load predication for the remainder, final 16-wide shfl
//   reduction, single coalesced 256B store. No atomics, no memset, no
//   intra-warp trip-count divergence.
//
// Inputs (metadata order):
//   d_in[0] = edge_index  [2, E]  int64 (or int32; runtime-detected)
//   d_in[1] = edge_feat   [E, 64] float32
//   d_in[2] = node_types  [N, 1]
// Output: [N, 64] float32

#define D_FEAT 64
#define LANES 16
#define BLOCK_THREADS 256
#define WARPS_PER_BLOCK (BLOCK_THREADS / 32)
#define KEYS_PER_THREAD 4
#define STEPS 8                     // edges per outer iter = 2 * STEPS = 16
#define MAX_NODES_P1 (1 << 21)

__device__ int g_offsets[MAX_NODES_P1];

// ---------------- Pass 1: CSR offsets from sorted keys ---------------------
__global__ void __launch_bounds__(256)
build_offsets_kernel(const void* __restrict__ edge_index, int E, int N)
{
    // dtype detection: an int64 read of an int32 buffer fuses two indices ->
    // value >= 2^32 >> N with overwhelming probability across 3 probes.
    __shared__ int s_is64;
    if (threadIdx.x == 0) {
        const long long* q = (const long long*)edge_index;
        unsigned long long v0 = (unsigned long long)q[E / 3];
        unsigned long long v1 = (unsigned long long)q[E / 2];
        unsigned long long v2 = (unsigned long long)q[E - 1];
        unsigned long long nn = (unsigned long long)N;
        s_is64 = (v0 < nn && v1 < nn && v2 < nn) ? 1 : 0;
    }
    __syncthreads();
    const bool is64 = (s_is64 != 0);

    const long long* __restrict__ p64 = (const long long*)edge_index;
    const int*       __restrict__ p32 = (const int*)edge_index;

    const int base = (blockIdx.x * blockDim.x + threadIdx.x) * KEYS_PER_THREAD;
    const int lane = threadIdx.x & 31;

    // Load this thread's keys (predicated; keep the whole warp converged
    // until after the shfl below).
    int k[KEYS_PER_THREAD];
    int nvalid = 0;
    if (base < E) {
        if (base + KEYS_PER_THREAD <= E) {
            nvalid = KEYS_PER_THREAD;
            if (is64) {
                longlong2 v0 = ((const longlong2*)p64)[(base >> 1) + 0];
                longlong2 v1 = ((const longlong2*)p64)[(base >> 1) + 1];
                k[0] = (int)v0.x; k[1] = (int)v0.y; k[2] = (int)v1.x; k[3] = (int)v1.y;
            } else {
                int4 v = ((const int4*)p32)[base >> 2];
                k[0] = v.x; k[1] = v.y; k[2] = v.z; k[3] = v.w;
            }
        } else {
            nvalid = E - base;
            #pragma unroll
            for (int j = 0; j < KEYS_PER_THREAD; ++j)
                if (j < nvalid) k[j] = is64 ? (int)p64[base + j] : p32[base + j];
        }
    }
    for (int j = nvalid; j < KEYS_PER_THREAD; ++j) k[j] = 0;  // shfl payload

    // prev key: neighbor thread's last key via shfl; lane 0 loads it.
    int prev = __shfl_up_sync(0xffffffffu, k[KEYS_PER_THREAD - 1], 1);
    if (lane == 0 && base > 0 && base <= E)
        prev = is64 ? (int)p64[base - 1] : p32[base - 1];
    if (base == 0) prev = -1;

    if (base >= E) return;

    #pragma unroll
    for (int j = 0; j < KEYS_PER_THREAD; ++j) {
        if (j < nvalid) {
            const int c = k[j];
            for (int n = prev + 1; n <= c; ++n) g_offsets[n] = base + j;
            prev = c;
        }
    }

    // Tail: nodes beyond the last key get empty ranges ending at E.
    if (base + nvalid == E) {
        for (int n = prev + 1; n <= N; ++n) g_offsets[n] = E;
    }
}

// ---------------- Pass 2: warp-per-node, 2 edges x float4 per step ---------
__global__ void __launch_bounds__(BLOCK_THREADS)
edgewise_reduce_kernel(const float4* __restrict__ feat,   // [E * LANES]
                       float4* __restrict__ out,          // [N * LANES]
                       int N)
{
    const int lane  = threadIdx.x & 31;
    const int sub   = lane >> 4;        // which edge of the pair (0/1)
    const int flane = lane & (LANES - 1);
    const int node  = blockIdx.x * WARPS_PER_BLOCK + (threadIdx.x >> 5);
    if (node >= N) return;

    const int start = g_offsets[node];
    const int end   = g_offsets[node + 1];

    float4 acc = make_float4(0.f, 0.f, 0.f, 0.f);

    #pragma unroll 1
    for (int e = start + sub; e < end; e += 2 * STEPS) {
        // 8 independent predicated LDG.128 per thread (128B in flight).
        #pragma unroll
        for (int i = 0; i < STEPS; ++i) {
            const int idx = e + 2 * i;
            if (idx < end) {
                float4 v = __ldg(&feat[(long long)idx * LANES + flane]);
                acc.x += v.x; acc.y += v.y; acc.z += v.z; acc.w += v.w;
            }
        }
    }

    // Combine the two edge-halves: lane l += lane l+16.
    acc.x += __shfl_down_sync(0xffffffffu, acc.x, 16);
    acc.y += __shfl_down_sync(0xffffffffu, acc.y, 16);
    acc.z += __shfl_down_sync(0xffffffffu, acc.z, 16);
    acc.w += __shfl_down_sync(0xffffffffu, acc.w, 16);

    if (sub == 0)
        out[(long long)node * LANES + flane] = acc;
}

extern "C" void kernel_launch(void* const* d_in, const int* in_sizes, int n_in,
                              void* d_out, int out_size)
{
    const void*   edge_index = d_in[0];
    const float4* feat       = (const float4*)d_in[1];
    float4*       out        = (float4*)d_out;

    const int E = in_sizes[1] / D_FEAT;
    const int N = out_size / D_FEAT;

    const int p1_threads = (E + KEYS_PER_THREAD - 1) / KEYS_PER_THREAD;
    build_offsets_kernel<<<(p1_threads + 255) / 256, 256>>>(edge_index, E, N);

    const int grid = (N + WARPS_PER_BLOCK - 1) / WARPS_PER_BLOCK;
    edgewise_reduce_kernel<<<grid, BLOCK_THREADS>>>(feat, out, N);
}